// round 6
// baseline (speedup 1.0000x reference)
#include <cuda_runtime.h>
#include <cuda_bf16.h>
#include <math.h>
#include <stdint.h>

#define B  8
#define H  512
#define W  512
#define PLANE (H*W)
#define NPIX (B*PLANE)

// ---------------------------------------------------------------------------
// Scratch
// ---------------------------------------------------------------------------
__device__ float g_f1[(size_t)B*32*PLANE];
__device__ float g_f2[(size_t)B*16*PLANE];
__device__ float g_f [(size_t)B* 8*PLANE];
__device__ float g_maps[(size_t)3*NPIX];
__device__ float g_fused[(size_t)NPIX];
__device__ unsigned g_h1[8192];
__device__ unsigned g_h2[4*8192];
__device__ unsigned g_h3[4*64];
__device__ float2 g_stats[32];
__device__ float g_thr[64];

// pre-split weights (tf32 big/small), fragment layouts
__device__ uint32_t g_w1b[9*4*32],  g_w1s[9*4*32];    // [s][k4][co32]
__device__ uint32_t g_w2b[4*9*8*16], g_w2s[4*9*8*16]; // [chunk][s][k8][m16]
__device__ uint32_t g_w3b[2*9*8*16], g_w3s[2*9*8*16]; // [chunk][s][k8][m16]

struct QState {
    unsigned pref1[4];
    unsigned rem[4];
    unsigned pref2[4];
    float q25, q75, iqr;
};
__device__ QState g_qs;

// ---------------------------------------------------------------------------
__global__ void zero_k() {
    int i = blockIdx.x * blockDim.x + threadIdx.x;
    int n = gridDim.x * blockDim.x;
    for (int j = i; j < 8192; j += n)    g_h1[j] = 0u;
    for (int j = i; j < 4*8192; j += n)  g_h2[j] = 0u;
    for (int j = i; j < 4*64; j += n)    g_h3[j] = 0u;
    for (int j = i; j < 32; j += n)      g_stats[j] = make_float2(0.f, 0.f);
}

__device__ __forceinline__ uint32_t f2tf(float f) {
    uint32_t r;
    asm("cvt.rna.tf32.f32 %0, %1;" : "=r"(r) : "f"(f));
    return r;
}
__device__ __forceinline__ void tf_split(float v, uint32_t& vb, uint32_t& vs) {
    vb = f2tf(v);
    vs = f2tf(v - __uint_as_float(vb));
}
__device__ __forceinline__ void mma8(float* d, const uint32_t* a, uint32_t b0, uint32_t b1) {
    asm("mma.sync.aligned.m16n8k8.row.col.f32.tf32.tf32.f32 "
        "{%0,%1,%2,%3}, {%4,%5,%6,%7}, {%8,%9}, {%0,%1,%2,%3};"
        : "+f"(d[0]), "+f"(d[1]), "+f"(d[2]), "+f"(d[3])
        : "r"(a[0]), "r"(a[1]), "r"(a[2]), "r"(a[3]), "r"(b0), "r"(b1));
}
__device__ __forceinline__ void mma4(float* d, uint32_t a0, uint32_t a1, uint32_t b0) {
    asm("mma.sync.aligned.m16n8k4.row.col.f32.tf32.tf32.f32 "
        "{%0,%1,%2,%3}, {%4,%5}, {%6}, {%0,%1,%2,%3};"
        : "+f"(d[0]), "+f"(d[1]), "+f"(d[2]), "+f"(d[3])
        : "r"(a0), "r"(a1), "r"(b0));
}
__device__ __forceinline__ float lrelu(float v) { return v >= 0.f ? v : 0.2f * v; }
__device__ __forceinline__ int uperm(int u) { return 2 * (u & 3) + (u >> 2); }

// ---------------------------------------------------------------------------
// Weight split pre-pass
// ---------------------------------------------------------------------------
__global__ void prep_k(const float* __restrict__ w1, const float* __restrict__ w2,
                       const float* __restrict__ w3) {
    int i0 = blockIdx.x * blockDim.x + threadIdx.x;
    int n = gridDim.x * blockDim.x;
    for (int j = i0; j < 9*4*32; j += n) {          // conv1 [s][k][co]
        int s = j / 128, k = (j >> 5) & 3, co = j & 31;
        tf_split(w1[co*36 + k*9 + s], g_w1b[j], g_w1s[j]);
    }
    for (int j = i0; j < 4*9*8*16; j += n) {        // conv2 [chunk][s][k][m]
        int chunk = j / 1152, r = j % 1152;
        int s = r / 128, k = (r >> 4) & 7, m = r & 15;
        tf_split(w2[m*288 + (chunk*8 + k)*9 + s], g_w2b[j], g_w2s[j]);
    }
    for (int j = i0; j < 2*9*8*16; j += n) {        // conv3 [chunk][s][k][m], m>=8 -> 0
        int chunk = j / 1152, r = j % 1152;
        int s = r / 128, k = (r >> 4) & 7, m = r & 15;
        float v = (m < 8) ? w3[m*144 + (chunk*8 + k)*9 + s] : 0.f;
        tf_split(v, g_w3b[j], g_w3s[j]);
    }
}

// ---------------------------------------------------------------------------
// conv1: 4 -> 32, leaky. Block 8 rows x 64 cols, 8 warps (1 row each).
// Tile pre-split in smem; weights from g_w1b/s.
// ---------------------------------------------------------------------------
__global__ __launch_bounds__(256, 2)
void conv1_k(const float* __restrict__ in, const float* __restrict__ bias,
             float* __restrict__ out) {
    __shared__ uint32_t tb[4*10*68], ts[4*10*68];
    const int tid = threadIdx.x;
    const int wid = tid >> 5, lane = tid & 31;
    const int nq = lane >> 2, tt = lane & 3;
    const int x0 = blockIdx.x * 64, y0 = blockIdx.y * 8, b = blockIdx.z;

    for (int i = tid; i < 4*10*66; i += 256) {
        int c = i / 660, rem = i % 660;
        int yy = rem / 66, xx = rem % 66;
        int gy = y0 + yy - 1, gx = x0 + xx - 1;
        float v = 0.f;
        if (gy >= 0 && gy < H && gx >= 0 && gx < W)
            v = in[(((size_t)b*4 + c)*H + gy)*W + gx];
        uint32_t vb, vs;
        tf_split(v, vb, vs);
        tb[c*680 + yy*68 + xx] = vb;
        ts[c*680 + yy*68 + xx] = vs;
    }
    __syncthreads();

    float acc[2][8][4];
#pragma unroll
    for (int m = 0; m < 2; m++)
#pragma unroll
        for (int g = 0; g < 8; g++)
#pragma unroll
            for (int q = 0; q < 4; q++) acc[m][g][q] = 0.f;

#pragma unroll
    for (int s = 0; s < 9; s++) {
        const int kh = s / 3, kw = s % 3;
        int wb = (s*4 + tt)*32;
        uint32_t a0b = g_w1b[wb + nq],      a1b = g_w1b[wb + nq + 8];
        uint32_t a2b = g_w1b[wb + 16 + nq], a3b = g_w1b[wb + 24 + nq];
        uint32_t a0s = g_w1s[wb + nq],      a1s = g_w1s[wb + nq + 8];
        uint32_t a2s = g_w1s[wb + 16 + nq], a3s = g_w1s[wb + 24 + nq];
        int base = tt*680 + (wid + kh)*68 + nq + kw;
#pragma unroll
        for (int g = 0; g < 8; g++) {
            uint32_t bb = tb[base + g*8];
            uint32_t bs = ts[base + g*8];
            mma4(acc[0][g], a0b, a1b, bb);
            mma4(acc[0][g], a0s, a1s, bb);
            mma4(acc[0][g], a0b, a1b, bs);
            mma4(acc[1][g], a2b, a3b, bb);
            mma4(acc[1][g], a2s, a3s, bb);
            mma4(acc[1][g], a2b, a3b, bs);
        }
    }

    const int gy = y0 + wid;
#pragma unroll
    for (int m = 0; m < 2; m++) {
        int co0 = m*16 + nq;
        float b0 = bias[co0], b1 = bias[co0 + 8];
#pragma unroll
        for (int g = 0; g < 8; g++) {
            int gx = x0 + g*8 + 2*tt;
            float2 o0, o1;
            o0.x = lrelu(acc[m][g][0] + b0); o0.y = lrelu(acc[m][g][1] + b0);
            o1.x = lrelu(acc[m][g][2] + b1); o1.y = lrelu(acc[m][g][3] + b1);
            *(float2*)&out[(((size_t)b*32 + co0)*H + gy)*W + gx] = o0;
            *(float2*)&out[(((size_t)b*32 + co0 + 8)*H + gy)*W + gx] = o1;
        }
    }
}

// ---------------------------------------------------------------------------
// conv2/conv3: k8 MMA, pixel-major interleaved split tiles (LDS.64 operands).
// Block 16 rows x 64 cols, 8 warps (2 rows each).
// ---------------------------------------------------------------------------
template<int CIN, int COUT, bool LEAKY>
__global__ __launch_bounds__(256, 2)
void convB_k(const float* __restrict__ in, const uint32_t* __restrict__ wbp,
             const uint32_t* __restrict__ wsp, const float* __restrict__ bias,
             float* __restrict__ out) {
    extern __shared__ uint32_t sm[];
    uint32_t* tb = sm;            // [18*66][8] interleaved
    uint32_t* ts = sm + 9504;
    const int tid = threadIdx.x;
    const int wid = tid >> 5, lane = tid & 31;
    const int nq = lane >> 2, tt = lane & 3;
    const int x0 = blockIdx.x * 64, y0 = blockIdx.y * 16, b = blockIdx.z;

    float acc[16][4];
#pragma unroll
    for (int g = 0; g < 16; g++)
#pragma unroll
        for (int q = 0; q < 4; q++) acc[g][q] = 0.f;

#pragma unroll 1
    for (int chunk = 0; chunk < CIN/8; chunk++) {
        __syncthreads();
        for (int i = tid; i < 8*18*66; i += 256) {
            int u = i / 1188, rem = i % 1188;
            int yy = rem / 66, xx = rem % 66;
            int gy = y0 + yy - 1, gx = x0 + xx - 1;
            float v = 0.f;
            if (gy >= 0 && gy < H && gx >= 0 && gx < W)
                v = in[(((size_t)b*CIN + chunk*8 + u)*H + gy)*W + gx];
            uint32_t vb, vs;
            tf_split(v, vb, vs);
            int t = (yy*66 + xx)*8 + uperm(u);
            tb[t] = vb; ts[t] = vs;
        }
        __syncthreads();

#pragma unroll
        for (int s = 0; s < 9; s++) {
            const int kh = s / 3, kw = s % 3;
            int wbase  = ((chunk*9 + s)*8 + tt)*16 + nq;
            int wbase4 = wbase + 4*16;
            uint32_t ab[4], as_[4];
            ab[0] = wbp[wbase];  ab[1] = wbp[wbase + 8];
            ab[2] = wbp[wbase4]; ab[3] = wbp[wbase4 + 8];
            as_[0] = wsp[wbase];  as_[1] = wsp[wbase + 8];
            as_[2] = wsp[wbase4]; as_[3] = wsp[wbase4 + 8];
#pragma unroll
            for (int g = 0; g < 16; g++) {
                int ty = 2*wid + (g >> 3) + kh;
                int tx = (g & 7)*8 + nq + kw;
                int t = (ty*66 + tx)*8 + 2*tt;
                uint2 Bb = *(const uint2*)&tb[t];
                uint2 Bs = *(const uint2*)&ts[t];
                mma8(acc[g], ab,  Bb.x, Bb.y);
                mma8(acc[g], as_, Bb.x, Bb.y);
                mma8(acc[g], ab,  Bs.x, Bs.y);
            }
        }
    }

    float b0 = bias[nq];
    float b1 = (COUT > 8) ? bias[nq + 8] : 0.f;
#pragma unroll
    for (int g = 0; g < 16; g++) {
        int gy = y0 + 2*wid + (g >> 3);
        int gx = x0 + (g & 7)*8 + 2*tt;
        float2 o0;
        o0.x = acc[g][0] + b0; o0.y = acc[g][1] + b0;
        if (LEAKY) { o0.x = lrelu(o0.x); o0.y = lrelu(o0.y); }
        *(float2*)&out[(((size_t)b*COUT + nq)*H + gy)*W + gx] = o0;
        if (COUT > 8) {
            float2 o1;
            o1.x = acc[g][2] + b1; o1.y = acc[g][3] + b1;
            if (LEAKY) { o1.x = lrelu(o1.x); o1.y = lrelu(o1.y); }
            *(float2*)&out[(((size_t)b*COUT + nq + 8)*H + gy)*W + gx] = o1;
        }
    }
}

// ---------------------------------------------------------------------------
// Multi-scale box std maps. 512 threads; 16 warps each own one full-width
// scan (channel c = w&7, quantity q = w>>3) per row. 2 barriers per row.
// ---------------------------------------------------------------------------
__device__ __forceinline__ int refl(int i) {
    return i < 0 ? -i : (i > H - 1 ? 2*(H - 1) - i : i);
}

__global__ __launch_bounds__(512)
void boxstd_k() {
    constexpr int ROWS = 64;
    extern __shared__ float bsm[];
    float* csA  = bsm;            // [8][512]
    float* csB  = bsm + 4096;     // [8][512]
    float* pref = bsm + 8192;     // [16][513]

    const int j    = threadIdx.x;
    const int lane = j & 31;
    const int wid  = j >> 5;
    const int strip = blockIdx.x;
    const int scale = blockIdx.y;
    const int b     = blockIdx.z;

    const int K = (scale == 0) ? 11 : (scale == 1) ? 25 : 49;
    const int P = K >> 1;
    const float inv = 1.f / (float)(K * K);
    const int r0 = strip * ROWS;

    for (int c = 0; c < 8; c++) {
        const float* fp = g_f + ((size_t)(b*8 + c)) * PLANE;
        float s = 0.f, s2 = 0.f;
        for (int i = r0 - P; i <= r0 + P; i++) {
            float v = fp[refl(i)*W + j];
            s += v;
            s2 = fmaf(v, v, s2);
        }
        csA[c*512 + j] = s;
        csB[c*512 + j] = s2;
    }

    const int sc = wid & 7, sq = wid >> 3;
    float* src = (sq ? csB : csA) + sc*512;
    float* pr  = pref + wid*513;

    for (int r = r0; r < r0 + ROWS; r++) {
        if (r > r0) {
            int ra = refl(r + P), rs = refl(r - 1 - P);
#pragma unroll
            for (int c = 0; c < 8; c++) {
                const float* fp = g_f + ((size_t)(b*8 + c)) * PLANE;
                float va = fp[ra*W + j], vs = fp[rs*W + j];
                csA[c*512 + j] += va - vs;
                csB[c*512 + j] += va*va - vs*vs;
            }
        }
        __syncthreads();

        // warp-owned full-width scan
        {
            float seg[16];
            float run = 0.f;
            int base = lane * 16;
#pragma unroll
            for (int i = 0; i < 16; i++) { run += src[base + i]; seg[i] = run; }
            float v = run;
#pragma unroll
            for (int d = 1; d < 32; d <<= 1) {
                float t = __shfl_up_sync(0xffffffffu, v, d);
                if (lane >= d) v += t;
            }
            float carry = v - run;
#pragma unroll
            for (int i = 0; i < 16; i++) pr[base + 1 + i] = seg[i] + carry;
            if (lane == 0) pr[0] = 0.f;
        }
        __syncthreads();

        const int lo = j - P, hi = j + P;
        const int loC = max(lo, 0), hiC = min(hi, W - 1);
        float rowacc = 0.f;
#pragma unroll
        for (int c = 0; c < 8; c++) {
            const float* pA = pref + c*513;
            const float* pB = pref + (8 + c)*513;
            float Sx = pA[hiC + 1] - pA[loC];
            float Sy = pB[hiC + 1] - pB[loC];
            if (lo < 0) {
                Sx += pA[-lo + 1] - pA[1];
                Sy += pB[-lo + 1] - pB[1];
            }
            if (hi > W - 1) {
                Sx += pA[W - 1] - pA[2*(W - 1) - hi];
                Sy += pB[W - 1] - pB[2*(W - 1) - hi];
            }
            float m  = Sx * inv;
            float m2 = Sy * inv;
            rowacc += sqrtf(fmaxf(m2 - m*m, 1e-6f));
        }
        g_maps[(size_t)scale*NPIX + ((size_t)b*H + r)*W + j] =
            powf(rowacc * 0.125f, 0.8f);
    }
}

// ---------------------------------------------------------------------------
// Fusion + level-1 histogram
// ---------------------------------------------------------------------------
__global__ void fuse_hist1_k(const float* __restrict__ fw, const float* __restrict__ fb) {
    __shared__ unsigned h[8192];
    for (int i = threadIdx.x; i < 8192; i += blockDim.x) h[i] = 0u;
    __syncthreads();
    const float w0 = fw[0], w1 = fw[1], w2 = fw[2], b0 = fb[0];
    const size_t N = NPIX;
    for (size_t i = (size_t)blockIdx.x*blockDim.x + threadIdx.x; i < N;
         i += (size_t)gridDim.x*blockDim.x) {
        float v = w0*g_maps[i] + w1*g_maps[i + N] + w2*g_maps[i + 2*N] + b0;
        v = fmaxf(v, 0.f);
        g_fused[i] = v;
        atomicAdd(&h[__float_as_uint(v) >> 19], 1u);
    }
    __syncthreads();
    for (int i = threadIdx.x; i < 8192; i += blockDim.x)
        if (h[i]) atomicAdd(&g_h1[i], h[i]);
}

__device__ void findRank(const unsigned* __restrict__ hist, int nbins, unsigned rank,
                         unsigned* sbin, unsigned* srem,
                         unsigned* sp, unsigned* sb) {
    __syncthreads();
    const int tid = threadIdx.x;
    const int chunk = nbins / 256;
    unsigned loc = 0;
    for (int i = 0; i < chunk; i++) loc += hist[tid*chunk + i];
    sp[tid] = loc;
    __syncthreads();
    if (tid == 0) {
        unsigned c = 0;
        for (int i = 0; i < 256; i++) { sb[i] = c; c += sp[i]; }
    }
    __syncthreads();
    unsigned cum = sb[tid];
    for (int i = 0; i < chunk; i++) {
        unsigned cnt = hist[tid*chunk + i];
        if (rank >= cum && rank < cum + cnt) { *sbin = tid*chunk + i; *srem = rank - cum; }
        cum += cnt;
    }
    __syncthreads();
}

__global__ void scan1_k() {
    __shared__ unsigned sp[256], sb[256];
    __shared__ unsigned rbin, rrem;
    const unsigned ranks[4] = {524287u, 524288u, 1572863u, 1572864u};
    for (int r = 0; r < 4; r++) {
        findRank(g_h1, 8192, ranks[r], &rbin, &rrem, sp, sb);
        if (threadIdx.x == 0) { g_qs.pref1[r] = rbin; g_qs.rem[r] = rrem; }
        __syncthreads();
    }
}

__global__ void hist2_k() {
    const int r = blockIdx.y;
    const unsigned pref = g_qs.pref1[r];
    __shared__ unsigned h[8192];
    for (int i = threadIdx.x; i < 8192; i += blockDim.x) h[i] = 0u;
    __syncthreads();
    for (size_t i = (size_t)blockIdx.x*blockDim.x + threadIdx.x; i < (size_t)NPIX;
         i += (size_t)gridDim.x*blockDim.x) {
        unsigned bits = __float_as_uint(g_fused[i]);
        if ((bits >> 19) == pref) atomicAdd(&h[(bits >> 6) & 8191u], 1u);
    }
    __syncthreads();
    for (int i = threadIdx.x; i < 8192; i += blockDim.x)
        if (h[i]) atomicAdd(&g_h2[r*8192 + i], h[i]);
}

__global__ void scan2_k() {
    __shared__ unsigned sp[256], sb[256];
    __shared__ unsigned rbin, rrem;
    for (int r = 0; r < 4; r++) {
        unsigned rank = g_qs.rem[r];
        findRank(g_h2 + r*8192, 8192, rank, &rbin, &rrem, sp, sb);
        if (threadIdx.x == 0) {
            g_qs.pref2[r] = (g_qs.pref1[r] << 13) | rbin;
            g_qs.rem[r]   = rrem;
        }
        __syncthreads();
    }
}

__global__ void hist3_k() {
    const int r = blockIdx.y;
    const unsigned pref = g_qs.pref2[r];
    __shared__ unsigned h[64];
    if (threadIdx.x < 64) h[threadIdx.x] = 0u;
    __syncthreads();
    for (size_t i = (size_t)blockIdx.x*blockDim.x + threadIdx.x; i < (size_t)NPIX;
         i += (size_t)gridDim.x*blockDim.x) {
        unsigned bits = __float_as_uint(g_fused[i]);
        if ((bits >> 6) == pref) atomicAdd(&h[bits & 63u], 1u);
    }
    __syncthreads();
    if (threadIdx.x < 64 && h[threadIdx.x]) atomicAdd(&g_h3[r*64 + threadIdx.x], h[threadIdx.x]);
}

__global__ void scan3_k() {
    __shared__ float sv[4];
    const int r = threadIdx.x;
    if (r < 4) {
        unsigned rank = g_qs.rem[r];
        unsigned cum = 0, bin = 0;
        for (int i = 0; i < 64; i++) {
            unsigned c = g_h3[r*64 + i];
            if (rank >= cum && rank < cum + c) bin = (unsigned)i;
            cum += c;
        }
        sv[r] = __uint_as_float((g_qs.pref2[r] << 6) | bin);
    }
    __syncthreads();
    if (r == 0) {
        float q25 = sv[0] + 0.75f*(sv[1] - sv[0]);
        float q75 = sv[2] + 0.25f*(sv[3] - sv[2]);
        float iqr = q75 - q25;
        if (iqr < 1e-5f) iqr = 0.05f;
        g_qs.q25 = q25; g_qs.q75 = q75; g_qs.iqr = iqr;
    }
}

__global__ void xstats_k(const float* __restrict__ x) {
    const int bc = blockIdx.x;
    const int sl = blockIdx.y;
    const float* p = x + ((size_t)bc << 18) + (size_t)sl * 32768;
    float s = 0.f, s2 = 0.f;
    for (int i = threadIdx.x; i < 32768; i += 256) {
        float v = p[i];
        s += v;
        s2 = fmaf(v, v, s2);
    }
#pragma unroll
    for (int o = 16; o; o >>= 1) {
        s  += __shfl_xor_sync(0xffffffffu, s, o);
        s2 += __shfl_xor_sync(0xffffffffu, s2, o);
    }
    __shared__ float ss[8], ss2[8];
    int w = threadIdx.x >> 5, l = threadIdx.x & 31;
    if (l == 0) { ss[w] = s; ss2[w] = s2; }
    __syncthreads();
    if (threadIdx.x == 0) {
        float a = 0.f, a2 = 0.f;
        for (int i = 0; i < 8; i++) { a += ss[i]; a2 += ss2[i]; }
        atomicAdd(&g_stats[bc].x, a);
        atomicAdd(&g_stats[bc].y, a2);
    }
}

__global__ void thr_k(const float* __restrict__ chw) {
    const int t = threadIdx.x;
    const int c = t & 3;
    float w0 = chw[0], w1 = chw[1], w2 = chw[2], w3 = chw[3];
    float mx = fmaxf(fmaxf(w0, w1), fmaxf(w2, w3));
    float e0 = expf(w0 - mx), e1 = expf(w1 - mx), e2 = expf(w2 - mx), e3 = expf(w3 - mx);
    float se = e0 + e1 + e2 + e3;
    float cw = ((c == 0) ? e0 : (c == 1) ? e1 : (c == 2) ? e2 : e3) / se;

    float2 st = g_stats[t];
    const float N = (float)PLANE;
    float var = (st.y - st.x*st.x/N) / (N - 1.f);
    float gstd = sqrtf(fmaxf(var, 0.f));

    float q25 = g_qs.q25, q75 = g_qs.q75, iqr = g_qs.iqr;
    float lower = q25 - 0.5f*iqr;
    float upper = q75 + 0.5f*iqr;
    float gf = fminf(fmaxf(gstd*5.f, 0.5f), 2.f);
    lower *= gf; upper *= gf;
    float cf = fminf(fmaxf(cw*gstd*2.f, 0.8f), 1.2f);
    lower *= cf; upper *= cf;

    float d = fabsf(upper - lower);
#pragma unroll
    for (int o = 16; o; o >>= 1) d = fminf(d, __shfl_xor_sync(0xffffffffu, d, o));
    if (d < 1e-5f) {
        float mt = 0.5f*(upper + lower);
        lower = mt - 0.05f;
        upper = mt + 0.05f;
    }
    g_thr[t]      = lower;
    g_thr[32 + t] = fmaxf(upper - lower, 1e-5f);
}

__global__ void mask_k(float* __restrict__ out) {
    for (size_t i = (size_t)blockIdx.x*blockDim.x + threadIdx.x; i < (size_t)NPIX;
         i += (size_t)gridDim.x*blockDim.x) {
        int b = (int)(i >> 18);
        float v = g_fused[i];
        float acc = 0.f;
#pragma unroll
        for (int c = 0; c < 4; c++) {
            float lo  = g_thr[b*4 + c];
            float dif = g_thr[32 + b*4 + c];
            float nrm = fminf(fmaxf((v - lo)/dif, 0.f), 1.f);
            acc += 1.f/(1.f + expf(3.f - 6.f*nrm));
        }
        out[i] = 0.25f*acc;
    }
}

// ---------------------------------------------------------------------------
// Launch
// ---------------------------------------------------------------------------
extern "C" void kernel_launch(void* const* d_in, const int* in_sizes, int n_in,
                              void* d_out, int out_size) {
    const float* x        = (const float*)d_in[0];
    const float* conv1_w  = (const float*)d_in[1];
    const float* conv1_b  = (const float*)d_in[2];
    const float* conv2_w  = (const float*)d_in[3];
    const float* conv2_b  = (const float*)d_in[4];
    const float* conv3_w  = (const float*)d_in[5];
    const float* conv3_b  = (const float*)d_in[6];
    const float* fusion_w = (const float*)d_in[7];
    const float* fusion_b = (const float*)d_in[8];
    const float* chw      = (const float*)d_in[9];
    float* out = (float*)d_out;

    float* f1; cudaGetSymbolAddress((void**)&f1, g_f1);
    float* f2; cudaGetSymbolAddress((void**)&f2, g_f2);
    float* f ; cudaGetSymbolAddress((void**)&f , g_f);
    uint32_t *w2b, *w2s, *w3b, *w3s;
    cudaGetSymbolAddress((void**)&w2b, g_w2b);
    cudaGetSymbolAddress((void**)&w2s, g_w2s);
    cudaGetSymbolAddress((void**)&w3b, g_w3b);
    cudaGetSymbolAddress((void**)&w3s, g_w3s);

    const int smemB  = 2 * 9504 * 4;   // 76032
    const int smemBX = (4096 + 4096 + 16*513) * 4;  // 65668
    cudaFuncSetAttribute(convB_k<32, 16, true>,  cudaFuncAttributeMaxDynamicSharedMemorySize, smemB);
    cudaFuncSetAttribute(convB_k<16, 8, false>,  cudaFuncAttributeMaxDynamicSharedMemorySize, smemB);
    cudaFuncSetAttribute(boxstd_k, cudaFuncAttributeMaxDynamicSharedMemorySize, smemBX);

    zero_k<<<64, 256>>>();
    prep_k<<<16, 256>>>(conv1_w, conv2_w, conv3_w);

    conv1_k<<<dim3(W/64, H/8, B), 256>>>(x, conv1_b, f1);
    convB_k<32, 16, true><<<dim3(W/64, H/16, B), 256, smemB>>>(f1, w2b, w2s, conv2_b, f2);
    convB_k<16, 8, false><<<dim3(W/64, H/16, B), 256, smemB>>>(f2, w3b, w3s, conv3_b, f);

    boxstd_k<<<dim3(H/64, 3, B), 512, smemBX>>>();

    fuse_hist1_k<<<192, 256>>>(fusion_w, fusion_b);
    scan1_k<<<1, 256>>>();
    hist2_k<<<dim3(64, 4), 256>>>();
    scan2_k<<<1, 256>>>();
    hist3_k<<<dim3(64, 4), 256>>>();
    scan3_k<<<1, 32>>>();

    xstats_k<<<dim3(32, 8), 256>>>(x);
    thr_k<<<1, 32>>>(chw);

    mask_k<<<1024, 256>>>(out);
}

// round 8
// speedup vs baseline: 1.2750x; 1.2750x over previous
#include <cuda_runtime.h>
#include <cuda_bf16.h>
#include <math.h>
#include <stdint.h>

#define B  8
#define H  512
#define W  512
#define PLANE (H*W)
#define NPIX (B*PLANE)

// ---------------------------------------------------------------------------
// Scratch
// ---------------------------------------------------------------------------
__device__ float g_f1[(size_t)B*32*PLANE];
__device__ float g_f2[(size_t)B*16*PLANE];
__device__ float g_f [(size_t)B* 8*PLANE];
__device__ float g_maps[(size_t)3*NPIX];
__device__ float g_fused[(size_t)NPIX];
__device__ unsigned g_h1[8192];
__device__ unsigned g_h2[4*8192];
__device__ unsigned g_h3[4*64];
__device__ float2 g_stats[32];
__device__ float g_thr[64];

// conv1 tf32 split weights [s][k4][co32]
__device__ uint32_t g_w1b[9*4*32], g_w1s[9*4*32];
// conv2/conv3 bf16x2 packed split weights:
// [chunk][s][tt4][nq8][reg4]  (reg = a0..a3 of m16n8k16)
__device__ __align__(16) uint32_t g_w2b[2*9*4*8*4], g_w2s[2*9*4*8*4];
__device__ __align__(16) uint32_t g_w3b[9*4*8*4],   g_w3s[9*4*8*4];

struct QState {
    unsigned pref1[4];
    unsigned rem[4];
    unsigned pref2[4];
    float q25, q75, iqr;
};
__device__ QState g_qs;

// ---------------------------------------------------------------------------
__global__ void zero_k() {
    int i = blockIdx.x * blockDim.x + threadIdx.x;
    int n = gridDim.x * blockDim.x;
    for (int j = i; j < 8192; j += n)    g_h1[j] = 0u;
    for (int j = i; j < 4*8192; j += n)  g_h2[j] = 0u;
    for (int j = i; j < 4*64; j += n)    g_h3[j] = 0u;
    for (int j = i; j < 32; j += n)      g_stats[j] = make_float2(0.f, 0.f);
}

__device__ __forceinline__ uint32_t f2tf(float f) {
    uint32_t r;
    asm("cvt.rna.tf32.f32 %0, %1;" : "=r"(r) : "f"(f));
    return r;
}
__device__ __forceinline__ void tf_split(float v, uint32_t& vb, uint32_t& vs) {
    vb = f2tf(v);
    vs = f2tf(v - __uint_as_float(vb));
}
// pack two values as bf16x2 big word; small (residual) word via out-param
__device__ __forceinline__ uint32_t bpack2(float v0, float v1, uint32_t& smw) {
    __nv_bfloat16 b0 = __float2bfloat16(v0), b1 = __float2bfloat16(v1);
    float r0 = v0 - __bfloat162float(b0);
    float r1 = v1 - __bfloat162float(b1);
    __nv_bfloat16 s0 = __float2bfloat16(r0), s1 = __float2bfloat16(r1);
    smw = (uint32_t)__bfloat16_as_ushort(s0) | ((uint32_t)__bfloat16_as_ushort(s1) << 16);
    return (uint32_t)__bfloat16_as_ushort(b0) | ((uint32_t)__bfloat16_as_ushort(b1) << 16);
}
__device__ __forceinline__ void mma16(float* d, const uint32_t* a, uint32_t b0, uint32_t b1) {
    asm("mma.sync.aligned.m16n8k16.row.col.f32.bf16.bf16.f32 "
        "{%0,%1,%2,%3}, {%4,%5,%6,%7}, {%8,%9}, {%0,%1,%2,%3};"
        : "+f"(d[0]), "+f"(d[1]), "+f"(d[2]), "+f"(d[3])
        : "r"(a[0]), "r"(a[1]), "r"(a[2]), "r"(a[3]), "r"(b0), "r"(b1));
}
__device__ __forceinline__ void mma4(float* d, uint32_t a0, uint32_t a1, uint32_t b0) {
    asm("mma.sync.aligned.m16n8k4.row.col.f32.tf32.tf32.f32 "
        "{%0,%1,%2,%3}, {%4,%5}, {%6}, {%0,%1,%2,%3};"
        : "+f"(d[0]), "+f"(d[1]), "+f"(d[2]), "+f"(d[3])
        : "r"(a0), "r"(a1), "r"(b0));
}
__device__ __forceinline__ float lrelu(float v) { return v >= 0.f ? v : 0.2f * v; }

// ---------------------------------------------------------------------------
// Weight prep
// ---------------------------------------------------------------------------
__global__ void prep_k(const float* __restrict__ w1, const float* __restrict__ w2,
                       const float* __restrict__ w3) {
    int i0 = blockIdx.x * blockDim.x + threadIdx.x;
    int n = gridDim.x * blockDim.x;
    // conv1 tf32 [s][k][co]
    for (int j = i0; j < 9*4*32; j += n) {
        int s = j / 128, k = (j >> 5) & 3, co = j & 31;
        tf_split(w1[co*36 + k*9 + s], g_w1b[j], g_w1s[j]);
    }
    // conv2 bf16 frags: j = (((chunk*9+s)*4+tt)*8+nq)*4+reg
    for (int j = i0; j < 2*9*4*8*4; j += n) {
        int reg = j & 3, nq = (j >> 2) & 7, tt = (j >> 5) & 3;
        int s = (j >> 7) % 9, chunk = j / 1152;
        int co = nq + (reg & 1) * 8;
        int ci = chunk*16 + 2*tt + (reg >> 1) * 8;
        float v0 = w2[co*288 + ci*9 + s];
        float v1 = w2[co*288 + (ci+1)*9 + s];
        uint32_t smw;
        uint32_t bg = bpack2(v0, v1, smw);
        g_w2b[j] = bg; g_w2s[j] = smw;
    }
    // conv3 bf16 frags (co >= 8 -> zero)
    for (int j = i0; j < 9*4*8*4; j += n) {
        int reg = j & 3, nq = (j >> 2) & 7, tt = (j >> 5) & 3;
        int s = (j >> 7) % 9;
        int co = nq + (reg & 1) * 8;
        int ci = 2*tt + (reg >> 1) * 8;
        float v0 = 0.f, v1 = 0.f;
        if (co < 8) {
            v0 = w3[co*144 + ci*9 + s];
            v1 = w3[co*144 + (ci+1)*9 + s];
        }
        uint32_t smw;
        uint32_t bg = bpack2(v0, v1, smw);
        g_w3b[j] = bg; g_w3s[j] = smw;
    }
}

// ---------------------------------------------------------------------------
// conv1: 4 -> 32, leaky (tf32 compensated, conflict-free already)
// ---------------------------------------------------------------------------
__global__ __launch_bounds__(256, 2)
void conv1_k(const float* __restrict__ in, const float* __restrict__ bias,
             float* __restrict__ out) {
    __shared__ uint32_t tb[4*10*68], ts[4*10*68];
    const int tid = threadIdx.x;
    const int wid = tid >> 5, lane = tid & 31;
    const int nq = lane >> 2, tt = lane & 3;
    const int x0 = blockIdx.x * 64, y0 = blockIdx.y * 8, b = blockIdx.z;

    for (int i = tid; i < 4*10*66; i += 256) {
        int c = i / 660, rem = i % 660;
        int yy = rem / 66, xx = rem % 66;
        int gy = y0 + yy - 1, gx = x0 + xx - 1;
        float v = 0.f;
        if (gy >= 0 && gy < H && gx >= 0 && gx < W)
            v = in[(((size_t)b*4 + c)*H + gy)*W + gx];
        uint32_t vb, vs;
        tf_split(v, vb, vs);
        tb[c*680 + yy*68 + xx] = vb;
        ts[c*680 + yy*68 + xx] = vs;
    }
    __syncthreads();

    float acc[2][8][4];
#pragma unroll
    for (int m = 0; m < 2; m++)
#pragma unroll
        for (int g = 0; g < 8; g++)
#pragma unroll
            for (int q = 0; q < 4; q++) acc[m][g][q] = 0.f;

#pragma unroll
    for (int s = 0; s < 9; s++) {
        const int kh = s / 3, kw = s % 3;
        int wb = (s*4 + tt)*32;
        uint32_t a0b = g_w1b[wb + nq],      a1b = g_w1b[wb + nq + 8];
        uint32_t a2b = g_w1b[wb + 16 + nq], a3b = g_w1b[wb + 24 + nq];
        uint32_t a0s = g_w1s[wb + nq],      a1s = g_w1s[wb + nq + 8];
        uint32_t a2s = g_w1s[wb + 16 + nq], a3s = g_w1s[wb + 24 + nq];
        int base = tt*680 + (wid + kh)*68 + nq + kw;
#pragma unroll
        for (int g = 0; g < 8; g++) {
            uint32_t bb = tb[base + g*8];
            uint32_t bs = ts[base + g*8];
            mma4(acc[0][g], a0b, a1b, bb);
            mma4(acc[0][g], a0s, a1s, bb);
            mma4(acc[0][g], a0b, a1b, bs);
            mma4(acc[1][g], a2b, a3b, bb);
            mma4(acc[1][g], a2s, a3s, bb);
            mma4(acc[1][g], a2b, a3b, bs);
        }
    }

    const int gy = y0 + wid;
#pragma unroll
    for (int m = 0; m < 2; m++) {
        int co0 = m*16 + nq;
        float b0 = bias[co0], b1 = bias[co0 + 8];
#pragma unroll
        for (int g = 0; g < 8; g++) {
            int gx = x0 + g*8 + 2*tt;
            float2 o0, o1;
            o0.x = lrelu(acc[m][g][0] + b0); o0.y = lrelu(acc[m][g][1] + b0);
            o1.x = lrelu(acc[m][g][2] + b1); o1.y = lrelu(acc[m][g][3] + b1);
            *(float2*)&out[(((size_t)b*32 + co0)*H + gy)*W + gx] = o0;
            *(float2*)&out[(((size_t)b*32 + co0 + 8)*H + gy)*W + gx] = o1;
        }
    }
}

// ---------------------------------------------------------------------------
// conv2/conv3: bf16 m16n8k16, 3-term compensated, 16 channels per chunk.
// Tile word u (channel pair 2u,2u+1) of pixel p stored at
//   p*8 + ((2*(u&3) + (u>>2) + 2*(p&3)) & 7)          (XOR-rotate swizzle)
// MMA B loads: LDS.64 at p*8 + ((2*tt + 2*(p&3)) & 7) — conflict-free.
// ---------------------------------------------------------------------------
template<int CIN, int COUT, bool LEAKY>
__global__ __launch_bounds__(256, 2)
void convB_k(const float* __restrict__ in, const uint4* __restrict__ wb4,
             const uint4* __restrict__ ws4, const float* __restrict__ bias,
             float* __restrict__ out) {
    extern __shared__ uint32_t sm[];
    uint32_t* tb = sm;            // [1188][8]
    uint32_t* ts = sm + 9504;
    const int tid = threadIdx.x;
    const int wid = tid >> 5, lane = tid & 31;
    const int nq = lane >> 2, tt = lane & 3;
    const int x0 = blockIdx.x * 64, y0 = blockIdx.y * 16, b = blockIdx.z;

    float acc[16][4];
#pragma unroll
    for (int g = 0; g < 16; g++)
#pragma unroll
        for (int q = 0; q < 4; q++) acc[g][q] = 0.f;

#pragma unroll 1
    for (int chunk = 0; chunk < CIN/16; chunk++) {
        __syncthreads();
        for (int i = tid; i < 8*1188; i += 256) {
            int u = i / 1188, pix = i - u*1188;
            int yy = pix / 66, xx = pix - yy*66;
            int gy = y0 + yy - 1, gx = x0 + xx - 1;
            float v0 = 0.f, v1 = 0.f;
            if (gy >= 0 && gy < H && gx >= 0 && gx < W) {
                size_t base = (((size_t)b*CIN + chunk*16 + 2*u)*H + gy)*W + gx;
                v0 = in[base];
                v1 = in[base + PLANE];
            }
            uint32_t sv;
            uint32_t bv = bpack2(v0, v1, sv);
            int pos = (2*(u & 3) + (u >> 2) + 2*(pix & 3)) & 7;
            int t = pix*8 + pos;
            tb[t] = bv; ts[t] = sv;
        }
        __syncthreads();

#pragma unroll
        for (int s = 0; s < 9; s++) {
            const int kh = s / 3, kw = s % 3;
            uint4 A = wb4[((chunk*9 + s)*4 + tt)*8 + nq];
            uint4 S = ws4[((chunk*9 + s)*4 + tt)*8 + nq];
            uint32_t ab[4]  = {A.x, A.y, A.z, A.w};
            uint32_t as_[4] = {S.x, S.y, S.z, S.w};
#pragma unroll
            for (int g = 0; g < 16; g++) {
                int ty = 2*wid + (g >> 3) + kh;
                int tx = (g & 7)*8 + nq + kw;
                int pix = ty*66 + tx;
                int t = pix*8 + ((2*tt + 2*(pix & 3)) & 7);
                uint2 Bb = *(const uint2*)&tb[t];
                uint2 Bs = *(const uint2*)&ts[t];
                mma16(acc[g], ab,  Bb.x, Bb.y);
                mma16(acc[g], as_, Bb.x, Bb.y);
                mma16(acc[g], ab,  Bs.x, Bs.y);
            }
        }
    }

    float b0 = bias[nq];
    float b1 = (COUT > 8) ? bias[nq + 8] : 0.f;
#pragma unroll
    for (int g = 0; g < 16; g++) {
        int gy = y0 + 2*wid + (g >> 3);
        int gx = x0 + (g & 7)*8 + 2*tt;
        float2 o0;
        o0.x = acc[g][0] + b0; o0.y = acc[g][1] + b0;
        if (LEAKY) { o0.x = lrelu(o0.x); o0.y = lrelu(o0.y); }
        *(float2*)&out[(((size_t)b*COUT + nq)*H + gy)*W + gx] = o0;
        if (COUT > 8) {
            float2 o1;
            o1.x = acc[g][2] + b1; o1.y = acc[g][3] + b1;
            if (LEAKY) { o1.x = lrelu(o1.x); o1.y = lrelu(o1.y); }
            *(float2*)&out[(((size_t)b*COUT + nq + 8)*H + gy)*W + gx] = o1;
        }
    }
}

// ---------------------------------------------------------------------------
// Multi-scale box std maps (16-warp full-width scans, 2 barriers/row)
// ---------------------------------------------------------------------------
__device__ __forceinline__ int refl(int i) {
    return i < 0 ? -i : (i > H - 1 ? 2*(H - 1) - i : i);
}

__global__ __launch_bounds__(512)
void boxstd_k() {
    constexpr int ROWS = 64;
    extern __shared__ float bsm[];
    float* csA  = bsm;            // [8][512]
    float* csB  = bsm + 4096;
    float* pref = bsm + 8192;     // [16][513]

    const int j    = threadIdx.x;
    const int lane = j & 31;
    const int wid  = j >> 5;
    const int strip = blockIdx.x;
    const int scale = blockIdx.y;
    const int b     = blockIdx.z;

    const int K = (scale == 0) ? 11 : (scale == 1) ? 25 : 49;
    const int P = K >> 1;
    const float inv = 1.f / (float)(K * K);
    const int r0 = strip * ROWS;

    for (int c = 0; c < 8; c++) {
        const float* fp = g_f + ((size_t)(b*8 + c)) * PLANE;
        float s = 0.f, s2 = 0.f;
        for (int i = r0 - P; i <= r0 + P; i++) {
            float v = fp[refl(i)*W + j];
            s += v;
            s2 = fmaf(v, v, s2);
        }
        csA[c*512 + j] = s;
        csB[c*512 + j] = s2;
    }

    const int sc = wid & 7, sq = wid >> 3;
    float* src = (sq ? csB : csA) + sc*512;
    float* pr  = pref + wid*513;

    for (int r = r0; r < r0 + ROWS; r++) {
        if (r > r0) {
            int ra = refl(r + P), rs = refl(r - 1 - P);
#pragma unroll
            for (int c = 0; c < 8; c++) {
                const float* fp = g_f + ((size_t)(b*8 + c)) * PLANE;
                float va = fp[ra*W + j], vs = fp[rs*W + j];
                csA[c*512 + j] += va - vs;
                csB[c*512 + j] += va*va - vs*vs;
            }
        }
        __syncthreads();

        {
            float seg[16];
            float run = 0.f;
            int base = lane * 16;
#pragma unroll
            for (int i = 0; i < 16; i++) { run += src[base + i]; seg[i] = run; }
            float v = run;
#pragma unroll
            for (int d = 1; d < 32; d <<= 1) {
                float t = __shfl_up_sync(0xffffffffu, v, d);
                if (lane >= d) v += t;
            }
            float carry = v - run;
#pragma unroll
            for (int i = 0; i < 16; i++) pr[base + 1 + i] = seg[i] + carry;
            if (lane == 0) pr[0] = 0.f;
        }
        __syncthreads();

        const int lo = j - P, hi = j + P;
        const int loC = max(lo, 0), hiC = min(hi, W - 1);
        float rowacc = 0.f;
#pragma unroll
        for (int c = 0; c < 8; c++) {
            const float* pA = pref + c*513;
            const float* pB = pref + (8 + c)*513;
            float Sx = pA[hiC + 1] - pA[loC];
            float Sy = pB[hiC + 1] - pB[loC];
            if (lo < 0) {
                Sx += pA[-lo + 1] - pA[1];
                Sy += pB[-lo + 1] - pB[1];
            }
            if (hi > W - 1) {
                Sx += pA[W - 1] - pA[2*(W - 1) - hi];
                Sy += pB[W - 1] - pB[2*(W - 1) - hi];
            }
            float m  = Sx * inv;
            float m2 = Sy * inv;
            rowacc += sqrtf(fmaxf(m2 - m*m, 1e-6f));
        }
        g_maps[(size_t)scale*NPIX + ((size_t)b*H + r)*W + j] =
            powf(rowacc * 0.125f, 0.8f);
    }
}

// ---------------------------------------------------------------------------
// Fusion + quantiles + stats + mask (unchanged)
// ---------------------------------------------------------------------------
__global__ void fuse_hist1_k(const float* __restrict__ fw, const float* __restrict__ fb) {
    __shared__ unsigned h[8192];
    for (int i = threadIdx.x; i < 8192; i += blockDim.x) h[i] = 0u;
    __syncthreads();
    const float w0 = fw[0], w1 = fw[1], w2 = fw[2], b0 = fb[0];
    const size_t N = NPIX;
    for (size_t i = (size_t)blockIdx.x*blockDim.x + threadIdx.x; i < N;
         i += (size_t)gridDim.x*blockDim.x) {
        float v = w0*g_maps[i] + w1*g_maps[i + N] + w2*g_maps[i + 2*N] + b0;
        v = fmaxf(v, 0.f);
        g_fused[i] = v;
        atomicAdd(&h[__float_as_uint(v) >> 19], 1u);
    }
    __syncthreads();
    for (int i = threadIdx.x; i < 8192; i += blockDim.x)
        if (h[i]) atomicAdd(&g_h1[i], h[i]);
}

__device__ void findRank(const unsigned* __restrict__ hist, int nbins, unsigned rank,
                         unsigned* sbin, unsigned* srem,
                         unsigned* sp, unsigned* sb) {
    __syncthreads();
    const int tid = threadIdx.x;
    const int chunk = nbins / 256;
    unsigned loc = 0;
    for (int i = 0; i < chunk; i++) loc += hist[tid*chunk + i];
    sp[tid] = loc;
    __syncthreads();
    if (tid == 0) {
        unsigned c = 0;
        for (int i = 0; i < 256; i++) { sb[i] = c; c += sp[i]; }
    }
    __syncthreads();
    unsigned cum = sb[tid];
    for (int i = 0; i < chunk; i++) {
        unsigned cnt = hist[tid*chunk + i];
        if (rank >= cum && rank < cum + cnt) { *sbin = tid*chunk + i; *srem = rank - cum; }
        cum += cnt;
    }
    __syncthreads();
}

__global__ void scan1_k() {
    __shared__ unsigned sp[256], sb[256];
    __shared__ unsigned rbin, rrem;
    const unsigned ranks[4] = {524287u, 524288u, 1572863u, 1572864u};
    for (int r = 0; r < 4; r++) {
        findRank(g_h1, 8192, ranks[r], &rbin, &rrem, sp, sb);
        if (threadIdx.x == 0) { g_qs.pref1[r] = rbin; g_qs.rem[r] = rrem; }
        __syncthreads();
    }
}

__global__ void hist2_k() {
    const int r = blockIdx.y;
    const unsigned pref = g_qs.pref1[r];
    __shared__ unsigned h[8192];
    for (int i = threadIdx.x; i < 8192; i += blockDim.x) h[i] = 0u;
    __syncthreads();
    for (size_t i = (size_t)blockIdx.x*blockDim.x + threadIdx.x; i < (size_t)NPIX;
         i += (size_t)gridDim.x*blockDim.x) {
        unsigned bits = __float_as_uint(g_fused[i]);
        if ((bits >> 19) == pref) atomicAdd(&h[(bits >> 6) & 8191u], 1u);
    }
    __syncthreads();
    for (int i = threadIdx.x; i < 8192; i += blockDim.x)
        if (h[i]) atomicAdd(&g_h2[r*8192 + i], h[i]);
}

__global__ void scan2_k() {
    __shared__ unsigned sp[256], sb[256];
    __shared__ unsigned rbin, rrem;
    for (int r = 0; r < 4; r++) {
        unsigned rank = g_qs.rem[r];
        findRank(g_h2 + r*8192, 8192, rank, &rbin, &rrem, sp, sb);
        if (threadIdx.x == 0) {
            g_qs.pref2[r] = (g_qs.pref1[r] << 13) | rbin;
            g_qs.rem[r]   = rrem;
        }
        __syncthreads();
    }
}

__global__ void hist3_k() {
    const int r = blockIdx.y;
    const unsigned pref = g_qs.pref2[r];
    __shared__ unsigned h[64];
    if (threadIdx.x < 64) h[threadIdx.x] = 0u;
    __syncthreads();
    for (size_t i = (size_t)blockIdx.x*blockDim.x + threadIdx.x; i < (size_t)NPIX;
         i += (size_t)gridDim.x*blockDim.x) {
        unsigned bits = __float_as_uint(g_fused[i]);
        if ((bits >> 6) == pref) atomicAdd(&h[bits & 63u], 1u);
    }
    __syncthreads();
    if (threadIdx.x < 64 && h[threadIdx.x]) atomicAdd(&g_h3[r*64 + threadIdx.x], h[threadIdx.x]);
}

__global__ void scan3_k() {
    __shared__ float sv[4];
    const int r = threadIdx.x;
    if (r < 4) {
        unsigned rank = g_qs.rem[r];
        unsigned cum = 0, bin = 0;
        for (int i = 0; i < 64; i++) {
            unsigned c = g_h3[r*64 + i];
            if (rank >= cum && rank < cum + c) bin = (unsigned)i;
            cum += c;
        }
        sv[r] = __uint_as_float((g_qs.pref2[r] << 6) | bin);
    }
    __syncthreads();
    if (r == 0) {
        float q25 = sv[0] + 0.75f*(sv[1] - sv[0]);
        float q75 = sv[2] + 0.25f*(sv[3] - sv[2]);
        float iqr = q75 - q25;
        if (iqr < 1e-5f) iqr = 0.05f;
        g_qs.q25 = q25; g_qs.q75 = q75; g_qs.iqr = iqr;
    }
}

__global__ void xstats_k(const float* __restrict__ x) {
    const int bc = blockIdx.x;
    const int sl = blockIdx.y;
    const float* p = x + ((size_t)bc << 18) + (size_t)sl * 32768;
    float s = 0.f, s2 = 0.f;
    for (int i = threadIdx.x; i < 32768; i += 256) {
        float v = p[i];
        s += v;
        s2 = fmaf(v, v, s2);
    }
#pragma unroll
    for (int o = 16; o; o >>= 1) {
        s  += __shfl_xor_sync(0xffffffffu, s, o);
        s2 += __shfl_xor_sync(0xffffffffu, s2, o);
    }
    __shared__ float ss[8], ss2[8];
    int w = threadIdx.x >> 5, l = threadIdx.x & 31;
    if (l == 0) { ss[w] = s; ss2[w] = s2; }
    __syncthreads();
    if (threadIdx.x == 0) {
        float a = 0.f, a2 = 0.f;
        for (int i = 0; i < 8; i++) { a += ss[i]; a2 += ss2[i]; }
        atomicAdd(&g_stats[bc].x, a);
        atomicAdd(&g_stats[bc].y, a2);
    }
}

__global__ void thr_k(const float* __restrict__ chw) {
    const int t = threadIdx.x;
    const int c = t & 3;
    float w0 = chw[0], w1 = chw[1], w2 = chw[2], w3 = chw[3];
    float mx = fmaxf(fmaxf(w0, w1), fmaxf(w2, w3));
    float e0 = expf(w0 - mx), e1 = expf(w1 - mx), e2 = expf(w2 - mx), e3 = expf(w3 - mx);
    float se = e0 + e1 + e2 + e3;
    float cw = ((c == 0) ? e0 : (c == 1) ? e1 : (c == 2) ? e2 : e3) / se;

    float2 st = g_stats[t];
    const float N = (float)PLANE;
    float var = (st.y - st.x*st.x/N) / (N - 1.f);
    float gstd = sqrtf(fmaxf(var, 0.f));

    float q25 = g_qs.q25, q75 = g_qs.q75, iqr = g_qs.iqr;
    float lower = q25 - 0.5f*iqr;
    float upper = q75 + 0.5f*iqr;
    float gf = fminf(fmaxf(gstd*5.f, 0.5f), 2.f);
    lower *= gf; upper *= gf;
    float cf = fminf(fmaxf(cw*gstd*2.f, 0.8f), 1.2f);
    lower *= cf; upper *= cf;

    float d = fabsf(upper - lower);
#pragma unroll
    for (int o = 16; o; o >>= 1) d = fminf(d, __shfl_xor_sync(0xffffffffu, d, o));
    if (d < 1e-5f) {
        float mt = 0.5f*(upper + lower);
        lower = mt - 0.05f;
        upper = mt + 0.05f;
    }
    g_thr[t]      = lower;
    g_thr[32 + t] = fmaxf(upper - lower, 1e-5f);
}

__global__ void mask_k(float* __restrict__ out) {
    for (size_t i = (size_t)blockIdx.x*blockDim.x + threadIdx.x; i < (size_t)NPIX;
         i += (size_t)gridDim.x*blockDim.x) {
        int b = (int)(i >> 18);
        float v = g_fused[i];
        float acc = 0.f;
#pragma unroll
        for (int c = 0; c < 4; c++) {
            float lo  = g_thr[b*4 + c];
            float dif = g_thr[32 + b*4 + c];
            float nrm = fminf(fmaxf((v - lo)/dif, 0.f), 1.f);
            acc += 1.f/(1.f + expf(3.f - 6.f*nrm));
        }
        out[i] = 0.25f*acc;
    }
}

// ---------------------------------------------------------------------------
// Launch
// ---------------------------------------------------------------------------
extern "C" void kernel_launch(void* const* d_in, const int* in_sizes, int n_in,
                              void* d_out, int out_size) {
    const float* x        = (const float*)d_in[0];
    const float* conv1_w  = (const float*)d_in[1];
    const float* conv1_b  = (const float*)d_in[2];
    const float* conv2_w  = (const float*)d_in[3];
    const float* conv2_b  = (const float*)d_in[4];
    const float* conv3_w  = (const float*)d_in[5];
    const float* conv3_b  = (const float*)d_in[6];
    const float* fusion_w = (const float*)d_in[7];
    const float* fusion_b = (const float*)d_in[8];
    const float* chw      = (const float*)d_in[9];
    float* out = (float*)d_out;

    float* f1; cudaGetSymbolAddress((void**)&f1, g_f1);
    float* f2; cudaGetSymbolAddress((void**)&f2, g_f2);
    float* f ; cudaGetSymbolAddress((void**)&f , g_f);
    uint4 *w2b, *w2s, *w3b, *w3s;
    cudaGetSymbolAddress((void**)&w2b, g_w2b);
    cudaGetSymbolAddress((void**)&w2s, g_w2s);
    cudaGetSymbolAddress((void**)&w3b, g_w3b);
    cudaGetSymbolAddress((void**)&w3s, g_w3s);

    const int smemB  = 2 * 9504 * 4;                 // 76032
    const int smemBX = (4096 + 4096 + 16*513) * 4;   // 65668
    cudaFuncSetAttribute(convB_k<32, 16, true>, cudaFuncAttributeMaxDynamicSharedMemorySize, smemB);
    cudaFuncSetAttribute(convB_k<16, 8, false>, cudaFuncAttributeMaxDynamicSharedMemorySize, smemB);
    cudaFuncSetAttribute(boxstd_k, cudaFuncAttributeMaxDynamicSharedMemorySize, smemBX);

    zero_k<<<64, 256>>>();
    prep_k<<<16, 256>>>(conv1_w, conv2_w, conv3_w);

    conv1_k<<<dim3(W/64, H/8, B), 256>>>(x, conv1_b, f1);
    convB_k<32, 16, true><<<dim3(W/64, H/16, B), 256, smemB>>>(x == 0 ? 0 : f1, w2b, w2s, conv2_b, f2);
    convB_k<16, 8, false><<<dim3(W/64, H/16, B), 256, smemB>>>(f2, w3b, w3s, conv3_b, f);

    boxstd_k<<<dim3(H/64, 3, B), 512, smemBX>>>();

    fuse_hist1_k<<<192, 256>>>(fusion_w, fusion_b);
    scan1_k<<<1, 256>>>();
    hist2_k<<<dim3(64, 4), 256>>>();
    scan2_k<<<1, 256>>>();
    hist3_k<<<dim3(64, 4), 256>>>();
    scan3_k<<<1, 32>>>();

    xstats_k<<<dim3(32, 8), 256>>>(x);
    thr_k<<<1, 32>>>(chw);

    mask_k<<<1024, 256>>>(out);
}

// round 11
// speedup vs baseline: 1.3486x; 1.0577x over previous
#include <cuda_runtime.h>
#include <cuda_bf16.h>
#include <math.h>
#include <stdint.h>

#define B  8
#define H  512
#define W  512
#define PLANE (H*W)
#define NPIX (B*PLANE)

// ---------------------------------------------------------------------------
// Scratch
// ---------------------------------------------------------------------------
// packed split activations: word = (bf16x2 big, bf16x2 small), pair (c, c+8)
__device__ __align__(16) uint2 g_f1p[(size_t)B*16*PLANE]; // [b][chunk2][u8][H][W]
__device__ __align__(16) uint2 g_f2p[(size_t)B* 8*PLANE]; // [b][u8][H][W]
__device__ float g_f [(size_t)B*8*PLANE];
__device__ float g_maps[(size_t)3*NPIX];
__device__ float g_fused[(size_t)NPIX];
__device__ unsigned g_h1[8192];
__device__ unsigned g_h2[4*8192];
__device__ unsigned g_h3[4*64];
__device__ float2 g_stats[32];
__device__ float g_thr[64];

// conv1 tf32 split weights [s][k4][co32]
__device__ uint32_t g_w1b[9*4*32], g_w1s[9*4*32];
// conv2/conv3 bf16x2 packed split weights [chunk][s][tt4][nq8][reg4]
__device__ __align__(16) uint32_t g_w2b[2*9*4*8*4], g_w2s[2*9*4*8*4];
__device__ __align__(16) uint32_t g_w3b[9*4*8*4],   g_w3s[9*4*8*4];

struct QState {
    unsigned pref1[4];
    unsigned rem[4];
    unsigned pref2[4];
    float q25, q75, iqr;
};
__device__ QState g_qs;

// ---------------------------------------------------------------------------
__global__ void zero_k() {
    int i = blockIdx.x * blockDim.x + threadIdx.x;
    int n = gridDim.x * blockDim.x;
    for (int j = i; j < 8192; j += n)    g_h1[j] = 0u;
    for (int j = i; j < 4*8192; j += n)  g_h2[j] = 0u;
    for (int j = i; j < 4*64; j += n)    g_h3[j] = 0u;
    for (int j = i; j < 32; j += n)      g_stats[j] = make_float2(0.f, 0.f);
}

__device__ __forceinline__ uint32_t f2tf(float f) {
    uint32_t r;
    asm("cvt.rna.tf32.f32 %0, %1;" : "=r"(r) : "f"(f));
    return r;
}
__device__ __forceinline__ void tf_split(float v, uint32_t& vb, uint32_t& vs) {
    vb = f2tf(v);
    vs = f2tf(v - __uint_as_float(vb));
}
__device__ __forceinline__ uint32_t bpack2(float v0, float v1, uint32_t& smw) {
    __nv_bfloat16 b0 = __float2bfloat16(v0), b1 = __float2bfloat16(v1);
    float r0 = v0 - __bfloat162float(b0);
    float r1 = v1 - __bfloat162float(b1);
    __nv_bfloat16 s0 = __float2bfloat16(r0), s1 = __float2bfloat16(r1);
    smw = (uint32_t)__bfloat16_as_ushort(s0) | ((uint32_t)__bfloat16_as_ushort(s1) << 16);
    return (uint32_t)__bfloat16_as_ushort(b0) | ((uint32_t)__bfloat16_as_ushort(b1) << 16);
}
__device__ __forceinline__ void mma16(float* d, const uint32_t* a, uint32_t b0, uint32_t b1) {
    asm("mma.sync.aligned.m16n8k16.row.col.f32.bf16.bf16.f32 "
        "{%0,%1,%2,%3}, {%4,%5,%6,%7}, {%8,%9}, {%0,%1,%2,%3};"
        : "+f"(d[0]), "+f"(d[1]), "+f"(d[2]), "+f"(d[3])
        : "r"(a[0]), "r"(a[1]), "r"(a[2]), "r"(a[3]), "r"(b0), "r"(b1));
}
__device__ __forceinline__ void mma4(float* d, uint32_t a0, uint32_t a1, uint32_t b0) {
    asm("mma.sync.aligned.m16n8k4.row.col.f32.tf32.tf32.f32 "
        "{%0,%1,%2,%3}, {%4,%5}, {%6}, {%0,%1,%2,%3};"
        : "+f"(d[0]), "+f"(d[1]), "+f"(d[2]), "+f"(d[3])
        : "r"(a0), "r"(a1), "r"(b0));
}
__device__ __forceinline__ float lrelu(float v) { return v >= 0.f ? v : 0.2f * v; }

// ---------------------------------------------------------------------------
// Weight prep. Pairing for bf16 path: word = channels (pu, pu+8).
// ---------------------------------------------------------------------------
__global__ void prep_k(const float* __restrict__ w1, const float* __restrict__ w2,
                       const float* __restrict__ w3) {
    int i0 = blockIdx.x * blockDim.x + threadIdx.x;
    int n = gridDim.x * blockDim.x;
    for (int j = i0; j < 9*4*32; j += n) {
        int s = j / 128, k = (j >> 5) & 3, co = j & 31;
        tf_split(w1[co*36 + k*9 + s], g_w1b[j], g_w1s[j]);
    }
    for (int j = i0; j < 2*9*4*8*4; j += n) {
        int reg = j & 3, nq = (j >> 2) & 7, tt = (j >> 5) & 3;
        int s = (j >> 7) % 9, chunk = j / 1152;
        int co = nq + 8*(reg & 1);
        int pu = tt + 4*(reg >> 1);
        float v0 = w2[co*288 + (chunk*16 + pu)*9 + s];
        float v1 = w2[co*288 + (chunk*16 + pu + 8)*9 + s];
        uint32_t smw;
        uint32_t bg = bpack2(v0, v1, smw);
        g_w2b[j] = bg; g_w2s[j] = smw;
    }
    for (int j = i0; j < 9*4*8*4; j += n) {
        int reg = j & 3, nq = (j >> 2) & 7, tt = (j >> 5) & 3;
        int s = (j >> 7) % 9;
        int co = nq + 8*(reg & 1);
        int pu = tt + 4*(reg >> 1);
        float v0 = 0.f, v1 = 0.f;
        if (co < 8) {
            v0 = w3[co*144 + pu*9 + s];
            v1 = w3[co*144 + (pu + 8)*9 + s];
        }
        uint32_t smw;
        uint32_t bg = bpack2(v0, v1, smw);
        g_w3b[j] = bg; g_w3s[j] = smw;
    }
}

// ---------------------------------------------------------------------------
// conv1: 4 -> 32, leaky. tf32 compensated; merged (big,small) uint2 tile.
// Epilogue writes packed split pairs (c, c+8) for conv2.
// ---------------------------------------------------------------------------
__global__ __launch_bounds__(256, 2)
void conv1_k(const float* __restrict__ in, const float* __restrict__ bias) {
    __shared__ uint2 t1[4*684];           // ch stride 684 (conflict-free LDS.64)
    const int tid = threadIdx.x;
    const int wid = tid >> 5, lane = tid & 31;
    const int nq = lane >> 2, tt = lane & 3;
    const int x0 = blockIdx.x * 64, y0 = blockIdx.y * 8, b = blockIdx.z;

    for (int i = tid; i < 4*10*66; i += 256) {
        int c = i / 660, rem = i % 660;
        int yy = rem / 66, xx = rem % 66;
        int gy = y0 + yy - 1, gx = x0 + xx - 1;
        float v = 0.f;
        if (gy >= 0 && gy < H && gx >= 0 && gx < W)
            v = in[(((size_t)b*4 + c)*H + gy)*W + gx];
        uint32_t vb, vs;
        tf_split(v, vb, vs);
        t1[c*684 + yy*68 + xx] = make_uint2(vb, vs);
    }
    __syncthreads();

    float acc[2][8][4];
#pragma unroll
    for (int m = 0; m < 2; m++)
#pragma unroll
        for (int g = 0; g < 8; g++)
#pragma unroll
            for (int q = 0; q < 4; q++) acc[m][g][q] = 0.f;

#pragma unroll
    for (int s = 0; s < 9; s++) {
        const int kh = s / 3, kw = s % 3;
        int wb = (s*4 + tt)*32;
        uint32_t a0b = g_w1b[wb + nq],      a1b = g_w1b[wb + nq + 8];
        uint32_t a2b = g_w1b[wb + 16 + nq], a3b = g_w1b[wb + 24 + nq];
        uint32_t a0s = g_w1s[wb + nq],      a1s = g_w1s[wb + nq + 8];
        uint32_t a2s = g_w1s[wb + 16 + nq], a3s = g_w1s[wb + 24 + nq];
        int base = tt*684 + (wid + kh)*68 + nq + kw;
#pragma unroll
        for (int g = 0; g < 8; g++) {
            uint2 bv = t1[base + g*8];
            mma4(acc[0][g], a0b, a1b, bv.x);
            mma4(acc[0][g], a0s, a1s, bv.x);
            mma4(acc[0][g], a0b, a1b, bv.y);
            mma4(acc[1][g], a2b, a3b, bv.x);
            mma4(acc[1][g], a2s, a3s, bv.x);
            mma4(acc[1][g], a2b, a3b, bv.y);
        }
    }

    const int gy = y0 + wid;
#pragma unroll
    for (int m = 0; m < 2; m++) {
        int co0 = m*16 + nq;
        float b0 = bias[co0], b8 = bias[co0 + 8];
        size_t plane = (size_t)(b*16 + m*8 + nq);
#pragma unroll
        for (int g = 0; g < 8; g++) {
            int pe = x0 + g*8 + 2*tt;
            float v0 = lrelu(acc[m][g][0] + b0);   // co, even px
            float v1 = lrelu(acc[m][g][1] + b0);   // co, odd px
            float v2 = lrelu(acc[m][g][2] + b8);   // co+8, even
            float v3 = lrelu(acc[m][g][3] + b8);   // co+8, odd
            uint32_t se, so;
            uint32_t be = bpack2(v0, v2, se);
            uint32_t bo = bpack2(v1, v3, so);
            *(uint4*)&g_f1p[plane*PLANE + (size_t)gy*W + pe] = make_uint4(be, se, bo, so);
        }
    }
}

// ---------------------------------------------------------------------------
// conv2/conv3: bf16 m16n8k16, 3-term compensated.
// Tile = uint2 slots (big,small). Pair u (<4) at even slot 2*((u+rr)&3),
// partner u+4 at +1, rr(pix) = (pix + pix>>2) & 3. Mainloop: one LDS.128
// yields (big_lo, small_lo, big_hi, small_hi).
// ---------------------------------------------------------------------------
template<int CHUNKS, int COUT, bool LEAKY, bool PACKOUT>
__global__ __launch_bounds__(256, 2)
void convP_k(const uint2* __restrict__ inp, const uint4* __restrict__ wb4,
             const uint4* __restrict__ ws4, const float* __restrict__ bias,
             uint2* __restrict__ outp, float* __restrict__ outf) {
    extern __shared__ uint2 tile[];   // [1188*8]
    const int tid = threadIdx.x;
    const int wid = tid >> 5, lane = tid & 31;
    const int nq = lane >> 2, tt = lane & 3;
    const int x0 = blockIdx.x * 64, y0 = blockIdx.y * 16, b = blockIdx.z;

    float acc[16][4];
#pragma unroll
    for (int g = 0; g < 16; g++)
#pragma unroll
        for (int q = 0; q < 4; q++) acc[g][q] = 0.f;

#pragma unroll 1
    for (int chunk = 0; chunk < CHUNKS; chunk++) {
        __syncthreads();
        for (int i = tid; i < 8*1188; i += 256) {
            int u = i / 1188, pix = i - u*1188;
            int yy = pix / 66, xx = pix - yy*66;
            int gy = y0 + yy - 1, gx = x0 + xx - 1;
            uint2 v = make_uint2(0u, 0u);
            if (gy >= 0 && gy < H && gx >= 0 && gx < W)
                v = inp[(((size_t)b*CHUNKS + chunk)*8 + u)*PLANE + (size_t)gy*W + gx];
            int rr = (pix + (pix >> 2)) & 3;
            int pos = 2*(((u & 3) + rr) & 3) + (u >> 2);
            tile[pix*8 + pos] = v;
        }
        __syncthreads();

#pragma unroll
        for (int s = 0; s < 9; s++) {
            const int kh = s / 3, kw = s % 3;
            uint4 A = wb4[((chunk*9 + s)*4 + tt)*8 + nq];
            uint4 S = ws4[((chunk*9 + s)*4 + tt)*8 + nq];
            uint32_t ab[4]  = {A.x, A.y, A.z, A.w};
            uint32_t as_[4] = {S.x, S.y, S.z, S.w};
#pragma unroll
            for (int g = 0; g < 16; g++) {
                int ty = 2*wid + (g >> 3) + kh;
                int tx = (g & 7)*8 + nq + kw;
                int pix = ty*66 + tx;
                int rr = (pix + (pix >> 2)) & 3;
                int t = pix*8 + 2*((tt + rr) & 3);
                uint4 Bv = *(const uint4*)&tile[t];
                mma16(acc[g], ab,  Bv.x, Bv.z);
                mma16(acc[g], as_, Bv.x, Bv.z);
                mma16(acc[g], ab,  Bv.y, Bv.w);
            }
        }
    }

    if (PACKOUT) {
        float b0 = bias[nq], b8 = bias[nq + 8];
        size_t plane = (size_t)(b*8 + nq);
#pragma unroll
        for (int g = 0; g < 16; g++) {
            int gy = y0 + 2*wid + (g >> 3);
            int pe = x0 + (g & 7)*8 + 2*tt;
            float v0 = acc[g][0] + b0, v1 = acc[g][1] + b0;
            float v2 = acc[g][2] + b8, v3 = acc[g][3] + b8;
            if (LEAKY) { v0 = lrelu(v0); v1 = lrelu(v1); v2 = lrelu(v2); v3 = lrelu(v3); }
            uint32_t se, so;
            uint32_t be = bpack2(v0, v2, se);
            uint32_t bo = bpack2(v1, v3, so);
            *(uint4*)&outp[plane*PLANE + (size_t)gy*W + pe] = make_uint4(be, se, bo, so);
        }
    } else {
        float b0 = bias[nq];
#pragma unroll
        for (int g = 0; g < 16; g++) {
            int gy = y0 + 2*wid + (g >> 3);
            int pe = x0 + (g & 7)*8 + 2*tt;
            float2 o0;
            o0.x = acc[g][0] + b0; o0.y = acc[g][1] + b0;
            if (LEAKY) { o0.x = lrelu(o0.x); o0.y = lrelu(o0.y); }
            *(float2*)&outf[(((size_t)b*COUT + nq)*H + gy)*W + pe] = o0;
        }
    }
}

// ---------------------------------------------------------------------------
// Multi-scale box std maps (16-warp full-width scans, 2 barriers/row)
// ---------------------------------------------------------------------------
__device__ __forceinline__ int refl(int i) {
    return i < 0 ? -i : (i > H - 1 ? 2*(H - 1) - i : i);
}

__global__ __launch_bounds__(512)
void boxstd_k() {
    constexpr int ROWS = 64;
    extern __shared__ float bsm[];
    float* csA  = bsm;
    float* csB  = bsm + 4096;
    float* pref = bsm + 8192;

    const int j    = threadIdx.x;
    const int lane = j & 31;
    const int wid  = j >> 5;
    const int strip = blockIdx.x;
    const int scale = blockIdx.y;
    const int b     = blockIdx.z;

    const int K = (scale == 0) ? 11 : (scale == 1) ? 25 : 49;
    const int P = K >> 1;
    const float inv = 1.f / (float)(K * K);
    const int r0 = strip * ROWS;

    for (int c = 0; c < 8; c++) {
        const float* fp = g_f + ((size_t)(b*8 + c)) * PLANE;
        float s = 0.f, s2 = 0.f;
        for (int i = r0 - P; i <= r0 + P; i++) {
            float v = fp[refl(i)*W + j];
            s += v;
            s2 = fmaf(v, v, s2);
        }
        csA[c*512 + j] = s;
        csB[c*512 + j] = s2;
    }

    const int sc = wid & 7, sq = wid >> 3;
    float* src = (sq ? csB : csA) + sc*512;
    float* pr  = pref + wid*513;

    for (int r = r0; r < r0 + ROWS; r++) {
        if (r > r0) {
            int ra = refl(r + P), rs = refl(r - 1 - P);
#pragma unroll
            for (int c = 0; c < 8; c++) {
                const float* fp = g_f + ((size_t)(b*8 + c)) * PLANE;
                float va = fp[ra*W + j], vs = fp[rs*W + j];
                csA[c*512 + j] += va - vs;
                csB[c*512 + j] += va*va - vs*vs;
            }
        }
        __syncthreads();

        {
            float seg[16];
            float run = 0.f;
            int base = lane * 16;
#pragma unroll
            for (int i = 0; i < 16; i++) { run += src[base + i]; seg[i] = run; }
            float v = run;
#pragma unroll
            for (int d = 1; d < 32; d <<= 1) {
                float t = __shfl_up_sync(0xffffffffu, v, d);
                if (lane >= d) v += t;
            }
            float carry = v - run;
#pragma unroll
            for (int i = 0; i < 16; i++) pr[base + 1 + i] = seg[i] + carry;
            if (lane == 0) pr[0] = 0.f;
        }
        __syncthreads();

        const int lo = j - P, hi = j + P;
        const int loC = max(lo, 0), hiC = min(hi, W - 1);
        float rowacc = 0.f;
#pragma unroll
        for (int c = 0; c < 8; c++) {
            const float* pA = pref + c*513;
            const float* pB = pref + (8 + c)*513;
            float Sx = pA[hiC + 1] - pA[loC];
            float Sy = pB[hiC + 1] - pB[loC];
            if (lo < 0) {
                Sx += pA[-lo + 1] - pA[1];
                Sy += pB[-lo + 1] - pB[1];
            }
            if (hi > W - 1) {
                Sx += pA[W - 1] - pA[2*(W - 1) - hi];
                Sy += pB[W - 1] - pB[2*(W - 1) - hi];
            }
            float m  = Sx * inv;
            float m2 = Sy * inv;
            rowacc += sqrtf(fmaxf(m2 - m*m, 1e-6f));
        }
        g_maps[(size_t)scale*NPIX + ((size_t)b*H + r)*W + j] =
            powf(rowacc * 0.125f, 0.8f);
    }
}

// ---------------------------------------------------------------------------
// Fusion + quantiles + stats + mask
// ---------------------------------------------------------------------------
__global__ void fuse_hist1_k(const float* __restrict__ fw, const float* __restrict__ fb) {
    __shared__ unsigned h[8192];
    for (int i = threadIdx.x; i < 8192; i += blockDim.x) h[i] = 0u;
    __syncthreads();
    const float w0 = fw[0], w1 = fw[1], w2 = fw[2], b0 = fb[0];
    const size_t N = NPIX;
    for (size_t i = (size_t)blockIdx.x*blockDim.x + threadIdx.x; i < N;
         i += (size_t)gridDim.x*blockDim.x) {
        float v = w0*g_maps[i] + w1*g_maps[i + N] + w2*g_maps[i + 2*N] + b0;
        v = fmaxf(v, 0.f);
        g_fused[i] = v;
        atomicAdd(&h[__float_as_uint(v) >> 19], 1u);
    }
    __syncthreads();
    for (int i = threadIdx.x; i < 8192; i += blockDim.x)
        if (h[i]) atomicAdd(&g_h1[i], h[i]);
}

__device__ void findRank(const unsigned* __restrict__ hist, int nbins, unsigned rank,
                         unsigned* sbin, unsigned* srem,
                         unsigned* sp, unsigned* sb) {
    __syncthreads();
    const int tid = threadIdx.x;
    const int chunk = nbins / 256;
    unsigned loc = 0;
    for (int i = 0; i < chunk; i++) loc += hist[tid*chunk + i];
    sp[tid] = loc;
    __syncthreads();
    if (tid == 0) {
        unsigned c = 0;
        for (int i = 0; i < 256; i++) { sb[i] = c; c += sp[i]; }
    }
    __syncthreads();
    unsigned cum = sb[tid];
    for (int i = 0; i < chunk; i++) {
        unsigned cnt = hist[tid*chunk + i];
        if (rank >= cum && rank < cum + cnt) { *sbin = tid*chunk + i; *srem = rank - cum; }
        cum += cnt;
    }
    __syncthreads();
}

__global__ void scan1_k() {
    __shared__ unsigned sp[256], sb[256];
    __shared__ unsigned rbin, rrem;
    const unsigned ranks[4] = {524287u, 524288u, 1572863u, 1572864u};
    for (int r = 0; r < 4; r++) {
        findRank(g_h1, 8192, ranks[r], &rbin, &rrem, sp, sb);
        if (threadIdx.x == 0) { g_qs.pref1[r] = rbin; g_qs.rem[r] = rrem; }
        __syncthreads();
    }
}

__global__ void hist2_k() {
    const int r = blockIdx.y;
    const unsigned pref = g_qs.pref1[r];
    __shared__ unsigned h[8192];
    for (int i = threadIdx.x; i < 8192; i += blockDim.x) h[i] = 0u;
    __syncthreads();
    for (size_t i = (size_t)blockIdx.x*blockDim.x + threadIdx.x; i < (size_t)NPIX;
         i += (size_t)gridDim.x*blockDim.x) {
        unsigned bits = __float_as_uint(g_fused[i]);
        if ((bits >> 19) == pref) atomicAdd(&h[(bits >> 6) & 8191u], 1u);
    }
    __syncthreads();
    for (int i = threadIdx.x; i < 8192; i += blockDim.x)
        if (h[i]) atomicAdd(&g_h2[r*8192 + i], h[i]);
}

__global__ void scan2_k() {
    __shared__ unsigned sp[256], sb[256];
    __shared__ unsigned rbin, rrem;
    for (int r = 0; r < 4; r++) {
        unsigned rank = g_qs.rem[r];
        findRank(g_h2 + r*8192, 8192, rank, &rbin, &rrem, sp, sb);
        if (threadIdx.x == 0) {
            g_qs.pref2[r] = (g_qs.pref1[r] << 13) | rbin;
            g_qs.rem[r]   = rrem;
        }
        __syncthreads();
    }
}

__global__ void hist3_k() {
    const int r = blockIdx.y;
    const unsigned pref = g_qs.pref2[r];
    __shared__ unsigned h[64];
    if (threadIdx.x < 64) h[threadIdx.x] = 0u;
    __syncthreads();
    for (size_t i = (size_t)blockIdx.x*blockDim.x + threadIdx.x; i < (size_t)NPIX;
         i += (size_t)gridDim.x*blockDim.x) {
        unsigned bits = __float_as_uint(g_fused[i]);
        if ((bits >> 6) == pref) atomicAdd(&h[bits & 63u], 1u);
    }
    __syncthreads();
    if (threadIdx.x < 64 && h[threadIdx.x]) atomicAdd(&g_h3[r*64 + threadIdx.x], h[threadIdx.x]);
}

__global__ void scan3_k() {
    __shared__ float sv[4];
    const int r = threadIdx.x;
    if (r < 4) {
        unsigned rank = g_qs.rem[r];
        unsigned cum = 0, bin = 0;
        for (int i = 0; i < 64; i++) {
            unsigned c = g_h3[r*64 + i];
            if (rank >= cum && rank < cum + c) bin = (unsigned)i;
            cum += c;
        }
        sv[r] = __uint_as_float((g_qs.pref2[r] << 6) | bin);
    }
    __syncthreads();
    if (r == 0) {
        float q25 = sv[0] + 0.75f*(sv[1] - sv[0]);
        float q75 = sv[2] + 0.25f*(sv[3] - sv[2]);
        float iqr = q75 - q25;
        if (iqr < 1e-5f) iqr = 0.05f;
        g_qs.q25 = q25; g_qs.q75 = q75; g_qs.iqr = iqr;
    }
}

__global__ void xstats_k(const float* __restrict__ x) {
    const int bc = blockIdx.x;
    const int sl = blockIdx.y;
    const float* p = x + ((size_t)bc << 18) + (size_t)sl * 32768;
    float s = 0.f, s2 = 0.f;
    for (int i = threadIdx.x; i < 32768; i += 256) {
        float v = p[i];
        s += v;
        s2 = fmaf(v, v, s2);
    }
#pragma unroll
    for (int o = 16; o; o >>= 1) {
        s  += __shfl_xor_sync(0xffffffffu, s, o);
        s2 += __shfl_xor_sync(0xffffffffu, s2, o);
    }
    __shared__ float ss[8], ss2[8];
    int w = threadIdx.x >> 5, l = threadIdx.x & 31;
    if (l == 0) { ss[w] = s; ss2[w] = s2; }
    __syncthreads();
    if (threadIdx.x == 0) {
        float a = 0.f, a2 = 0.f;
        for (int i = 0; i < 8; i++) { a += ss[i]; a2 += ss2[i]; }
        atomicAdd(&g_stats[bc].x, a);
        atomicAdd(&g_stats[bc].y, a2);
    }
}

__global__ void thr_k(const float* __restrict__ chw) {
    const int t = threadIdx.x;
    const int c = t & 3;
    float w0 = chw[0], w1 = chw[1], w2 = chw[2], w3 = chw[3];
    float mx = fmaxf(fmaxf(w0, w1), fmaxf(w2, w3));
    float e0 = expf(w0 - mx), e1 = expf(w1 - mx), e2 = expf(w2 - mx), e3 = expf(w3 - mx);
    float se = e0 + e1 + e2 + e3;
    float cw = ((c == 0) ? e0 : (c == 1) ? e1 : (c == 2) ? e2 : e3) / se;

    float2 st = g_stats[t];
    const float N = (float)PLANE;
    float var = (st.y - st.x*st.x/N) / (N - 1.f);
    float gstd = sqrtf(fmaxf(var, 0.f));

    float q25 = g_qs.q25, q75 = g_qs.q75, iqr = g_qs.iqr;
    float lower = q25 - 0.5f*iqr;
    float upper = q75 + 0.5f*iqr;
    float gf = fminf(fmaxf(gstd*5.f, 0.5f), 2.f);
    lower *= gf; upper *= gf;
    float cf = fminf(fmaxf(cw*gstd*2.f, 0.8f), 1.2f);
    lower *= cf; upper *= cf;

    float d = fabsf(upper - lower);
#pragma unroll
    for (int o = 16; o; o >>= 1) d = fminf(d, __shfl_xor_sync(0xffffffffu, d, o));
    if (d < 1e-5f) {
        float mt = 0.5f*(upper + lower);
        lower = mt - 0.05f;
        upper = mt + 0.05f;
    }
    g_thr[t]      = lower;
    g_thr[32 + t] = fmaxf(upper - lower, 1e-5f);
}

__global__ void mask_k(float* __restrict__ out) {
    for (size_t i = (size_t)blockIdx.x*blockDim.x + threadIdx.x; i < (size_t)NPIX;
         i += (size_t)gridDim.x*blockDim.x) {
        int b = (int)(i >> 18);
        float v = g_fused[i];
        float acc = 0.f;
#pragma unroll
        for (int c = 0; c < 4; c++) {
            float lo  = g_thr[b*4 + c];
            float dif = g_thr[32 + b*4 + c];
            float nrm = fminf(fmaxf((v - lo)/dif, 0.f), 1.f);
            acc += 1.f/(1.f + expf(3.f - 6.f*nrm));
        }
        out[i] = 0.25f*acc;
    }
}

// ---------------------------------------------------------------------------
// Launch
// ---------------------------------------------------------------------------
extern "C" void kernel_launch(void* const* d_in, const int* in_sizes, int n_in,
                              void* d_out, int out_size) {
    const float* x        = (const float*)d_in[0];
    const float* conv1_w  = (const float*)d_in[1];
    const float* conv1_b  = (const float*)d_in[2];
    const float* conv2_w  = (const float*)d_in[3];
    const float* conv2_b  = (const float*)d_in[4];
    const float* conv3_w  = (const float*)d_in[5];
    const float* conv3_b  = (const float*)d_in[6];
    const float* fusion_w = (const float*)d_in[7];
    const float* fusion_b = (const float*)d_in[8];
    const float* chw      = (const float*)d_in[9];
    float* out = (float*)d_out;

    uint2* f1p; cudaGetSymbolAddress((void**)&f1p, g_f1p);
    uint2* f2p; cudaGetSymbolAddress((void**)&f2p, g_f2p);
    float* f  ; cudaGetSymbolAddress((void**)&f  , g_f);
    uint4 *w2b, *w2s, *w3b, *w3s;
    cudaGetSymbolAddress((void**)&w2b, g_w2b);
    cudaGetSymbolAddress((void**)&w2s, g_w2s);
    cudaGetSymbolAddress((void**)&w3b, g_w3b);
    cudaGetSymbolAddress((void**)&w3s, g_w3s);

    const int smemP  = 1188 * 8 * 8;                 // 76032
    const int smemBX = (4096 + 4096 + 16*513) * 4;   // 65668
    cudaFuncSetAttribute(convP_k<2, 16, true, true>,  cudaFuncAttributeMaxDynamicSharedMemorySize, smemP);
    cudaFuncSetAttribute(convP_k<1, 8, false, false>, cudaFuncAttributeMaxDynamicSharedMemorySize, smemP);
    cudaFuncSetAttribute(boxstd_k, cudaFuncAttributeMaxDynamicSharedMemorySize, smemBX);

    zero_k<<<64, 256>>>();
    prep_k<<<16, 256>>>(conv1_w, conv2_w, conv3_w);

    conv1_k<<<dim3(W/64, H/8, B), 256>>>(x, conv1_b);
    convP_k<2, 16, true, true><<<dim3(W/64, H/16, B), 256, smemP>>>(f1p, w2b, w2s, conv2_b, f2p, 0);
    convP_k<1, 8, false, false><<<dim3(W/64, H/16, B), 256, smemP>>>(f2p, w3b, w3s, conv3_b, 0, f);

    boxstd_k<<<dim3(H/64, 3, B), 512, smemBX>>>();

    fuse_hist1_k<<<192, 256>>>(fusion_w, fusion_b);
    scan1_k<<<1, 256>>>();
    hist2_k<<<dim3(64, 4), 256>>>();
    scan2_k<<<1, 256>>>();
    hist3_k<<<dim3(64, 4), 256>>>();
    scan3_k<<<1, 32>>>();

    xstats_k<<<dim3(32, 8), 256>>>(x);
    thr_k<<<1, 32>>>(chw);

    mask_k<<<1024, 256>>>(out);
}